// round 3
// baseline (speedup 1.0000x reference)
#include <cuda_runtime.h>
#include <math_constants.h>

#define NB 8
#define NP 4096
#define THREADS 128
#define ILX2 4                   // packed f32x2 x-points per thread (= 8 scalar)
#define XCHUNK (THREADS * ILX2 * 2)  // 1024
#define XC (NP / XCHUNK)         // 4
#define YT 1024
#define YC (NP / YT)             // 4

#define FMA_F32X2(d, a, b, c) \
    asm("fma.rn.f32x2 %0, %1, %2, %3;" : "=l"(d) : "l"(a), "l"(b), "l"(c))
#define PACK_F32X2(out, lo, hi) \
    asm("mov.b64 %0, {%1, %2};" : "=l"(out) : "f"(lo), "f"(hi))
#define UNPACK_F32X2(lo, hi, in) \
    asm("mov.b64 {%0, %1}, %2;" : "=f"(lo), "=f"(hi) : "l"(in))

// Per-point running mins (both directions), stored as monotone-transformed
// int bits so atomicMin gives float-min ordering even for slightly-negative
// distances (the xx+yy-2xy form can round below zero).
__device__ int g_min[2 * NB * NP];

__device__ __forceinline__ int float_key(float f) {
    int i = __float_as_int(f);
    return i < 0 ? (i ^ 0x7FFFFFFF) : i;
}

__global__ void init_min_kernel() {
    int i = blockIdx.x * blockDim.x + threadIdx.x;
    if (i < 2 * NB * NP) g_min[i] = 0x7F800000;  // +inf (positive: key == bits)
}

__global__ __launch_bounds__(THREADS) void chamfer_kernel(
    const float* __restrict__ x, const float* __restrict__ y) {
    // Pre-duplicated packed operands: {-2px,-2px}, {-2py,-2py}, {-2pz,-2pz}, {pp,pp}
    __shared__ float2 sm2x[YT], sm2y[YT], sm2z[YT], spp[YT];  // 32 KB

    const int yc   = blockIdx.x;
    const int xc   = blockIdx.y;
    const int dirb = blockIdx.z;
    const int dir  = dirb >> 3;
    const int b    = dirb & 7;

    const float* A  = dir ? y : x;
    const float* P  = dir ? x : y;
    const float* Ab = A + b * 3 * NP;
    const float* Pb = P + b * 3 * NP;

    const int tid = threadIdx.x;

    // Stage point tile: negate/scale and duplicate for packed math.
    for (int j = tid; j < YT; j += THREADS) {
        int gj = yc * YT + j;
        float px = Pb[gj], py = Pb[NP + gj], pz = Pb[2 * NP + gj];
        float pp = fmaf(pz, pz, fmaf(py, py, px * px));
        sm2x[j] = make_float2(-2.0f * px, -2.0f * px);
        sm2y[j] = make_float2(-2.0f * py, -2.0f * py);
        sm2z[j] = make_float2(-2.0f * pz, -2.0f * pz);
        spp[j]  = make_float2(pp, pp);
    }
    __syncthreads();

    unsigned long long ax2[ILX2], ay2[ILX2], az2[ILX2];
    float aa[2 * ILX2];
    float mn_lo[ILX2], mn_hi[ILX2];
#pragma unroll
    for (int k = 0; k < ILX2; k++) {
        int gi0 = xc * XCHUNK + (2 * k + 0) * THREADS + tid;
        int gi1 = xc * XCHUNK + (2 * k + 1) * THREADS + tid;
        float x0 = Ab[gi0],            x1 = Ab[gi1];
        float y0 = Ab[NP + gi0],       y1 = Ab[NP + gi1];
        float z0 = Ab[2 * NP + gi0],   z1 = Ab[2 * NP + gi1];
        PACK_F32X2(ax2[k], x0, x1);
        PACK_F32X2(ay2[k], y0, y1);
        PACK_F32X2(az2[k], z0, z1);
        aa[2 * k + 0] = fmaf(z0, z0, fmaf(y0, y0, x0 * x0));
        aa[2 * k + 1] = fmaf(z1, z1, fmaf(y1, y1, x1 * x1));
        mn_lo[k] = CUDART_INF_F;
        mn_hi[k] = CUDART_INF_F;
    }

#pragma unroll 2
    for (int j = 0; j < YT; j++) {
        unsigned long long mx = *reinterpret_cast<const unsigned long long*>(&sm2x[j]);
        unsigned long long my = *reinterpret_cast<const unsigned long long*>(&sm2y[j]);
        unsigned long long mz = *reinterpret_cast<const unsigned long long*>(&sm2z[j]);
        unsigned long long pp = *reinterpret_cast<const unsigned long long*>(&spp[j]);
#pragma unroll
        for (int k = 0; k < ILX2; k++) {
            unsigned long long t;
            FMA_F32X2(t, ax2[k], mx, pp);
            FMA_F32X2(t, ay2[k], my, t);
            FMA_F32X2(t, az2[k], mz, t);
            float lo, hi;
            UNPACK_F32X2(lo, hi, t);
            mn_lo[k] = fminf(mn_lo[k], lo);
            mn_hi[k] = fminf(mn_hi[k], hi);
        }
    }

    int* gm = g_min + (dir * NB + b) * NP;
#pragma unroll
    for (int k = 0; k < ILX2; k++) {
        int gi0 = xc * XCHUNK + (2 * k + 0) * THREADS + tid;
        int gi1 = xc * XCHUNK + (2 * k + 1) * THREADS + tid;
        atomicMin(&gm[gi0], float_key(aa[2 * k + 0] + mn_lo[k]));
        atomicMin(&gm[gi1], float_key(aa[2 * k + 1] + mn_hi[k]));
    }
}

__global__ void reduce_kernel(float* __restrict__ out) {
    __shared__ float sred[256];
    float s = 0.0f;
    for (int i = threadIdx.x; i < 2 * NB * NP; i += 256) {
        int v = g_min[i];
        v = v < 0 ? (v ^ 0x7FFFFFFF) : v;  // invert monotone transform
        s += __int_as_float(v);
    }
    sred[threadIdx.x] = s;
    __syncthreads();
    for (int w = 128; w > 0; w >>= 1) {
        if (threadIdx.x < w) sred[threadIdx.x] += sred[threadIdx.x + w];
        __syncthreads();
    }
    if (threadIdx.x == 0) {
        // mean_b( sum_minx/NP + sum_miny/NP ) = total_sum / (NB*NP)
        out[0] = sred[0] / (float)(NB * NP);
    }
}

extern "C" void kernel_launch(void* const* d_in, const int* in_sizes, int n_in,
                              void* d_out, int out_size) {
    const float* x = (const float*)d_in[0];
    const float* y = (const float*)d_in[1];
    float* out = (float*)d_out;

    init_min_kernel<<<(2 * NB * NP + 255) / 256, 256>>>();
    dim3 grid(YC, XC, 2 * NB);
    chamfer_kernel<<<grid, THREADS>>>(x, y);
    reduce_kernel<<<1, 256>>>(out);
}

// round 4
// speedup vs baseline: 1.8451x; 1.8451x over previous
#include <cuda_runtime.h>
#include <math_constants.h>

#define NB 8
#define NP 4096
#define THREADS 256
#define ILX2 4                        // packed f32x2 x-points per thread (= 8 scalar)
#define XCHUNK (THREADS * ILX2 * 2)   // 2048
#define XC (NP / XCHUNK)              // 2
#define YT 1024
#define YC (NP / YT)                  // 4
#define NDB (2 * NB)                  // 16 (dir, batch) pairs
#define RBLOCKS 64

#define FMA_F32X2(d, a, b, c) \
    asm("fma.rn.f32x2 %0, %1, %2, %3;" : "=l"(d) : "l"(a), "l"(b), "l"(c))
#define PACK_F32X2(out, lo, hi) \
    asm("mov.b64 %0, {%1, %2};" : "=l"(out) : "f"(lo), "f"(hi))
#define UNPACK_F32X2(lo, hi, in) \
    asm("mov.b64 {%0, %1}, %2;" : "=f"(lo), "=f"(hi) : "l"(in))

// Per-(dir,batch, y-tile) partial mins. Written with plain stores every
// launch (no init needed, no atomics).
__device__ float g_part[NDB * YC * NP];
__device__ float g_psum[RBLOCKS];

__global__ __launch_bounds__(THREADS) void chamfer_kernel(
    const float* __restrict__ x, const float* __restrict__ y) {
    // Pre-duplicated packed operands: {-2px,-2px}, {-2py,-2py}, {-2pz,-2pz}, {pp,pp}
    __shared__ float2 sm2x[YT], sm2y[YT], sm2z[YT], spp[YT];  // 32 KB

    const int yc   = blockIdx.x;
    const int xc   = blockIdx.y;
    const int dirb = blockIdx.z;
    const int dir  = dirb >> 3;
    const int b    = dirb & 7;

    const float* A  = dir ? y : x;
    const float* P  = dir ? x : y;
    const float* Ab = A + b * 3 * NP;
    const float* Pb = P + b * 3 * NP;

    const int tid = threadIdx.x;

    for (int j = tid; j < YT; j += THREADS) {
        int gj = yc * YT + j;
        float px = Pb[gj], py = Pb[NP + gj], pz = Pb[2 * NP + gj];
        float pp = fmaf(pz, pz, fmaf(py, py, px * px));
        float nx = -2.0f * px, ny = -2.0f * py, nz = -2.0f * pz;
        sm2x[j] = make_float2(nx, nx);
        sm2y[j] = make_float2(ny, ny);
        sm2z[j] = make_float2(nz, nz);
        spp[j]  = make_float2(pp, pp);
    }
    __syncthreads();

    unsigned long long ax2[ILX2], ay2[ILX2], az2[ILX2];
    float aa[2 * ILX2];
    float mn_lo[ILX2], mn_hi[ILX2];
#pragma unroll
    for (int k = 0; k < ILX2; k++) {
        int gi0 = xc * XCHUNK + (2 * k + 0) * THREADS + tid;
        int gi1 = xc * XCHUNK + (2 * k + 1) * THREADS + tid;
        float x0 = Ab[gi0],          x1 = Ab[gi1];
        float y0 = Ab[NP + gi0],     y1 = Ab[NP + gi1];
        float z0 = Ab[2 * NP + gi0], z1 = Ab[2 * NP + gi1];
        PACK_F32X2(ax2[k], x0, x1);
        PACK_F32X2(ay2[k], y0, y1);
        PACK_F32X2(az2[k], z0, z1);
        aa[2 * k + 0] = fmaf(z0, z0, fmaf(y0, y0, x0 * x0));
        aa[2 * k + 1] = fmaf(z1, z1, fmaf(y1, y1, x1 * x1));
        mn_lo[k] = CUDART_INF_F;
        mn_hi[k] = CUDART_INF_F;
    }

#pragma unroll 4
    for (int j = 0; j < YT; j++) {
        unsigned long long mx = *reinterpret_cast<const unsigned long long*>(&sm2x[j]);
        unsigned long long my = *reinterpret_cast<const unsigned long long*>(&sm2y[j]);
        unsigned long long mz = *reinterpret_cast<const unsigned long long*>(&sm2z[j]);
        unsigned long long pp = *reinterpret_cast<const unsigned long long*>(&spp[j]);
#pragma unroll
        for (int k = 0; k < ILX2; k++) {
            unsigned long long t;
            FMA_F32X2(t, ax2[k], mx, pp);
            FMA_F32X2(t, ay2[k], my, t);
            FMA_F32X2(t, az2[k], mz, t);
            float lo, hi;
            UNPACK_F32X2(lo, hi, t);
            mn_lo[k] = fminf(mn_lo[k], lo);
            mn_hi[k] = fminf(mn_hi[k], hi);
        }
    }

    // Plain stores into this block's private partial-min slice.
    float* gp = g_part + (dirb * YC + yc) * NP;
#pragma unroll
    for (int k = 0; k < ILX2; k++) {
        int gi0 = xc * XCHUNK + (2 * k + 0) * THREADS + tid;
        int gi1 = xc * XCHUNK + (2 * k + 1) * THREADS + tid;
        gp[gi0] = aa[2 * k + 0] + mn_lo[k];
        gp[gi1] = aa[2 * k + 1] + mn_hi[k];
    }
}

// Stage A: min over the YC partial tiles, accumulate per-block sums.
__global__ __launch_bounds__(256) void reduceA_kernel() {
    __shared__ float sred[256];
    const int tid = threadIdx.x;
    float s = 0.0f;
#pragma unroll
    for (int k = 0; k < 4; k++) {
        int pt = blockIdx.x * 1024 + k * 256 + tid;  // global point 0..65535
        int db = pt >> 12;
        int p  = pt & (NP - 1);
        const float* gp = g_part + db * YC * NP + p;
        float m = gp[0];
#pragma unroll
        for (int yc = 1; yc < YC; yc++) m = fminf(m, gp[yc * NP]);
        s += m;
    }
    sred[tid] = s;
    __syncthreads();
    for (int w = 128; w > 0; w >>= 1) {
        if (tid < w) sred[tid] += sred[tid + w];
        __syncthreads();
    }
    if (tid == 0) g_psum[blockIdx.x] = sred[0];
}

// Stage B: final scalar.
__global__ void reduceB_kernel(float* __restrict__ out) {
    __shared__ float sred[RBLOCKS];
    int tid = threadIdx.x;
    sred[tid] = g_psum[tid];
    __syncthreads();
    for (int w = RBLOCKS / 2; w > 0; w >>= 1) {
        if (tid < w) sred[tid] += sred[tid + w];
        __syncthreads();
    }
    if (tid == 0) out[0] = sred[0] / (float)(NB * NP);
}

extern "C" void kernel_launch(void* const* d_in, const int* in_sizes, int n_in,
                              void* d_out, int out_size) {
    const float* x = (const float*)d_in[0];
    const float* y = (const float*)d_in[1];
    float* out = (float*)d_out;

    dim3 grid(YC, XC, NDB);  // 4 x 2 x 16 = 128 blocks
    chamfer_kernel<<<grid, THREADS>>>(x, y);
    reduceA_kernel<<<RBLOCKS, 256>>>();
    reduceB_kernel<<<1, RBLOCKS>>>(out);
}

// round 5
// speedup vs baseline: 1.9803x; 1.0733x over previous
#include <cuda_runtime.h>
#include <math_constants.h>

#define NB 8
#define NP 4096
#define THREADS 256
#define ILX2 4                        // packed f32x2 x-points per thread (= 8 scalar)
#define XCHUNK (THREADS * ILX2 * 2)   // 2048
#define XC (NP / XCHUNK)              // 2
#define YT 512
#define YC (NP / YT)                  // 8
#define NDB (2 * NB)                  // 16 (dir, batch) pairs
#define RBLOCKS 64

#define FMA_F32X2(d, a, b, c) \
    asm("fma.rn.f32x2 %0, %1, %2, %3;" : "=l"(d) : "l"(a), "l"(b), "l"(c))
#define PACK_F32X2(out, lo, hi) \
    asm("mov.b64 %0, {%1, %2};" : "=l"(out) : "f"(lo), "f"(hi))
#define UNPACK_F32X2(lo, hi, in) \
    asm("mov.b64 {%0, %1}, %2;" : "=f"(lo), "=f"(hi) : "l"(in))

// Per-(dir,batch, y-tile) partial mins. Written with plain stores every
// launch (no init needed, no atomics).
__device__ float g_part[NDB * YC * NP];
__device__ float g_psum[RBLOCKS];

__global__ __launch_bounds__(THREADS) void chamfer_kernel(
    const float* __restrict__ x, const float* __restrict__ y) {
    // Pre-duplicated packed operands: {-2px,-2px}, {-2py,-2py}, {-2pz,-2pz}, {pp,pp}
    __shared__ float2 sm2x[YT], sm2y[YT], sm2z[YT], spp[YT];  // 16 KB

    const int yc   = blockIdx.x;
    const int xc   = blockIdx.y;
    const int dirb = blockIdx.z;
    const int dir  = dirb >> 3;
    const int b    = dirb & 7;

    const float* A  = dir ? y : x;
    const float* P  = dir ? x : y;
    const float* Ab = A + b * 3 * NP;
    const float* Pb = P + b * 3 * NP;

    const int tid = threadIdx.x;

    for (int j = tid; j < YT; j += THREADS) {
        int gj = yc * YT + j;
        float px = Pb[gj], py = Pb[NP + gj], pz = Pb[2 * NP + gj];
        float pp = fmaf(pz, pz, fmaf(py, py, px * px));
        float nx = -2.0f * px, ny = -2.0f * py, nz = -2.0f * pz;
        sm2x[j] = make_float2(nx, nx);
        sm2y[j] = make_float2(ny, ny);
        sm2z[j] = make_float2(nz, nz);
        spp[j]  = make_float2(pp, pp);
    }
    __syncthreads();

    unsigned long long ax2[ILX2], ay2[ILX2], az2[ILX2];
    float aa[2 * ILX2];
    float mn_lo[ILX2], mn_hi[ILX2];
#pragma unroll
    for (int k = 0; k < ILX2; k++) {
        int gi0 = xc * XCHUNK + (2 * k + 0) * THREADS + tid;
        int gi1 = xc * XCHUNK + (2 * k + 1) * THREADS + tid;
        float x0 = Ab[gi0],          x1 = Ab[gi1];
        float y0 = Ab[NP + gi0],     y1 = Ab[NP + gi1];
        float z0 = Ab[2 * NP + gi0], z1 = Ab[2 * NP + gi1];
        PACK_F32X2(ax2[k], x0, x1);
        PACK_F32X2(ay2[k], y0, y1);
        PACK_F32X2(az2[k], z0, z1);
        aa[2 * k + 0] = fmaf(z0, z0, fmaf(y0, y0, x0 * x0));
        aa[2 * k + 1] = fmaf(z1, z1, fmaf(y1, y1, x1 * x1));
        mn_lo[k] = CUDART_INF_F;
        mn_hi[k] = CUDART_INF_F;
    }

#pragma unroll 8
    for (int j = 0; j < YT; j++) {
        unsigned long long mx = *reinterpret_cast<const unsigned long long*>(&sm2x[j]);
        unsigned long long my = *reinterpret_cast<const unsigned long long*>(&sm2y[j]);
        unsigned long long mz = *reinterpret_cast<const unsigned long long*>(&sm2z[j]);
        unsigned long long pp = *reinterpret_cast<const unsigned long long*>(&spp[j]);
#pragma unroll
        for (int k = 0; k < ILX2; k++) {
            unsigned long long t;
            FMA_F32X2(t, ax2[k], mx, pp);
            FMA_F32X2(t, ay2[k], my, t);
            FMA_F32X2(t, az2[k], mz, t);
            float lo, hi;
            UNPACK_F32X2(lo, hi, t);
            mn_lo[k] = fminf(mn_lo[k], lo);
            mn_hi[k] = fminf(mn_hi[k], hi);
        }
    }

    // Plain stores into this block's private partial-min slice.
    float* gp = g_part + (dirb * YC + yc) * NP;
#pragma unroll
    for (int k = 0; k < ILX2; k++) {
        int gi0 = xc * XCHUNK + (2 * k + 0) * THREADS + tid;
        int gi1 = xc * XCHUNK + (2 * k + 1) * THREADS + tid;
        gp[gi0] = aa[2 * k + 0] + mn_lo[k];
        gp[gi1] = aa[2 * k + 1] + mn_hi[k];
    }
}

// Stage A: min over the YC partial tiles, accumulate per-block sums.
__global__ __launch_bounds__(256) void reduceA_kernel() {
    __shared__ float sred[256];
    const int tid = threadIdx.x;
    float s = 0.0f;
#pragma unroll
    for (int k = 0; k < 4; k++) {
        int pt = blockIdx.x * 1024 + k * 256 + tid;  // global point 0..65535
        int db = pt >> 12;
        int p  = pt & (NP - 1);
        const float* gp = g_part + db * YC * NP + p;
        float m = gp[0];
#pragma unroll
        for (int yc = 1; yc < YC; yc++) m = fminf(m, gp[yc * NP]);
        s += m;
    }
    sred[tid] = s;
    __syncthreads();
    for (int w = 128; w > 0; w >>= 1) {
        if (tid < w) sred[tid] += sred[tid + w];
        __syncthreads();
    }
    if (tid == 0) g_psum[blockIdx.x] = sred[0];
}

// Stage B: final scalar.
__global__ void reduceB_kernel(float* __restrict__ out) {
    __shared__ float sred[RBLOCKS];
    int tid = threadIdx.x;
    sred[tid] = g_psum[tid];
    __syncthreads();
    for (int w = RBLOCKS / 2; w > 0; w >>= 1) {
        if (tid < w) sred[tid] += sred[tid + w];
        __syncthreads();
    }
    if (tid == 0) out[0] = sred[0] / (float)(NB * NP);
}

extern "C" void kernel_launch(void* const* d_in, const int* in_sizes, int n_in,
                              void* d_out, int out_size) {
    const float* x = (const float*)d_in[0];
    const float* y = (const float*)d_in[1];
    float* out = (float*)d_out;

    dim3 grid(YC, XC, NDB);  // 8 x 2 x 16 = 256 blocks
    chamfer_kernel<<<grid, THREADS>>>(x, y);
    reduceA_kernel<<<RBLOCKS, 256>>>();
    reduceB_kernel<<<1, RBLOCKS>>>(out);
}

// round 7
// speedup vs baseline: 2.1512x; 1.0863x over previous
#include <cuda_runtime.h>
#include <math_constants.h>

#define NB 8
#define NP 4096
#define THREADS 256
#define ILX 4                        // scalar x-points per thread (duplicated-packed)
#define XCHUNK (THREADS * ILX)       // 1024
#define XC (NP / XCHUNK)             // 4
#define YT 512
#define YP (YT / 2)                  // 256 j-pairs
#define YC (NP / YT)                 // 8
#define NDB (2 * NB)                 // 16 (dir, batch) pairs
#define RBLOCKS 64

#define FMA_F32X2(d, a, b, c) \
    asm("fma.rn.f32x2 %0, %1, %2, %3;" : "=l"(d) : "l"(a), "l"(b), "l"(c))
#define PACK_F32X2(out, lo, hi) \
    asm("mov.b64 %0, {%1, %2};" : "=l"(out) : "f"(lo), "f"(hi))
#define UNPACK_F32X2(lo, hi, in) \
    asm("mov.b64 {%0, %1}, %2;" : "=f"(lo), "=f"(hi) : "l"(in))

// Per-(dir,batch,y-tile) partial mins. Plain stores, no init, no atomics.
__device__ float g_part[NDB * YC * NP];
__device__ float g_psum[RBLOCKS];

__global__ __launch_bounds__(THREADS) void chamfer_kernel(
    const float* __restrict__ x, const float* __restrict__ y) {
    // Two y-points per entry, laid out so one LDS.128 yields two packed
    // f32x2 operands directly:
    //   sA[jp] = {nx_j0, nx_j1, ny_j0, ny_j1}
    //   sB[jp] = {nz_j0, nz_j1, pp_j0, pp_j1}
    __shared__ float4 sA[YP], sB[YP];  // 8 KB

    const int yc   = blockIdx.x;
    const int xc   = blockIdx.y;
    const int dirb = blockIdx.z;
    const int dir  = dirb >> 3;
    const int b    = dirb & 7;

    const float* A  = dir ? y : x;
    const float* P  = dir ? x : y;
    const float* Ab = A + b * 3 * NP;
    const float* Pb = P + b * 3 * NP;

    const int tid = threadIdx.x;

    // Stage y-tile: each thread handles one j-pair.
    for (int jp = tid; jp < YP; jp += THREADS) {
        int g0 = yc * YT + 2 * jp;
        int g1 = g0 + 1;
        float px0 = Pb[g0],          px1 = Pb[g1];
        float py0 = Pb[NP + g0],     py1 = Pb[NP + g1];
        float pz0 = Pb[2 * NP + g0], pz1 = Pb[2 * NP + g1];
        float pp0 = fmaf(pz0, pz0, fmaf(py0, py0, px0 * px0));
        float pp1 = fmaf(pz1, pz1, fmaf(py1, py1, px1 * px1));
        sA[jp] = make_float4(-2.0f * px0, -2.0f * px1, -2.0f * py0, -2.0f * py1);
        sB[jp] = make_float4(-2.0f * pz0, -2.0f * pz1, pp0, pp1);
    }
    __syncthreads();

    // Duplicated-packed x operands (loop invariant).
    unsigned long long axd[ILX], ayd[ILX], azd[ILX];
    float aa[ILX], mn[ILX];
#pragma unroll
    for (int k = 0; k < ILX; k++) {
        int gi = xc * XCHUNK + k * THREADS + tid;
        float ax = Ab[gi], ay = Ab[NP + gi], az = Ab[2 * NP + gi];
        PACK_F32X2(axd[k], ax, ax);
        PACK_F32X2(ayd[k], ay, ay);
        PACK_F32X2(azd[k], az, az);
        aa[k] = fmaf(az, az, fmaf(ay, ay, ax * ax));
        mn[k] = CUDART_INF_F;
    }

#pragma unroll 4
    for (int jp = 0; jp < YP; jp++) {
        ulonglong2 va = *reinterpret_cast<const ulonglong2*>(&sA[jp]);
        ulonglong2 vb = *reinterpret_cast<const ulonglong2*>(&sB[jp]);
        const unsigned long long mx = va.x;  // {nx0, nx1}
        const unsigned long long my = va.y;  // {ny0, ny1}
        const unsigned long long mz = vb.x;  // {nz0, nz1}
        const unsigned long long pp = vb.y;  // {pp0, pp1}
#pragma unroll
        for (int k = 0; k < ILX; k++) {
            unsigned long long t;
            FMA_F32X2(t, axd[k], mx, pp);
            FMA_F32X2(t, ayd[k], my, t);
            FMA_F32X2(t, azd[k], mz, t);
            float lo, hi;
            UNPACK_F32X2(lo, hi, t);
            mn[k] = fminf(mn[k], lo);
            mn[k] = fminf(mn[k], hi);
        }
    }

    float* gp = g_part + (dirb * YC + yc) * NP;
#pragma unroll
    for (int k = 0; k < ILX; k++) {
        int gi = xc * XCHUNK + k * THREADS + tid;
        gp[gi] = aa[k] + mn[k];
    }
}

// Stage A: min over the YC partial tiles, accumulate per-block sums.
__global__ __launch_bounds__(256) void reduceA_kernel() {
    __shared__ float sred[256];
    const int tid = threadIdx.x;
    float s = 0.0f;
#pragma unroll
    for (int k = 0; k < 4; k++) {
        int pt = blockIdx.x * 1024 + k * 256 + tid;  // global point 0..65535
        int db = pt >> 12;
        int p  = pt & (NP - 1);
        const float* gp = g_part + db * YC * NP + p;
        float m = gp[0];
#pragma unroll
        for (int yc = 1; yc < YC; yc++) m = fminf(m, gp[yc * NP]);
        s += m;
    }
    sred[tid] = s;
    __syncthreads();
    for (int w = 128; w > 0; w >>= 1) {
        if (tid < w) sred[tid] += sred[tid + w];
        __syncthreads();
    }
    if (tid == 0) g_psum[blockIdx.x] = sred[0];
}

// Stage B: final scalar.
__global__ void reduceB_kernel(float* __restrict__ out) {
    __shared__ float sred[RBLOCKS];
    int tid = threadIdx.x;
    sred[tid] = g_psum[tid];
    __syncthreads();
    for (int w = RBLOCKS / 2; w > 0; w >>= 1) {
        if (tid < w) sred[tid] += sred[tid + w];
        __syncthreads();
    }
    if (tid == 0) out[0] = sred[0] / (float)(NB * NP);
}

extern "C" void kernel_launch(void* const* d_in, const int* in_sizes, int n_in,
                              void* d_out, int out_size) {
    const float* x = (const float*)d_in[0];
    const float* y = (const float*)d_in[1];
    float* out = (float*)d_out;

    dim3 grid(YC, XC, NDB);  // 8 x 4 x 16 = 512 blocks
    chamfer_kernel<<<grid, THREADS>>>(x, y);
    reduceA_kernel<<<RBLOCKS, 256>>>();
    reduceB_kernel<<<1, RBLOCKS>>>(out);
}

// round 8
// speedup vs baseline: 2.2553x; 1.0484x over previous
#include <cuda_runtime.h>
#include <math_constants.h>

#define NB 8
#define NP 4096
#define THREADS 256
#define ILX 4                        // scalar x-points per thread (duplicated-packed)
#define XCHUNK (THREADS * ILX)       // 1024
#define XC (NP / XCHUNK)             // 4
#define YT 256
#define YP (YT / 2)                  // 128 j-pairs
#define YC (NP / YT)                 // 16
#define NDB (2 * NB)                 // 16 (dir, batch) pairs
#define RBLOCKS 64

#define FMA_F32X2(d, a, b, c) \
    asm("fma.rn.f32x2 %0, %1, %2, %3;" : "=l"(d) : "l"(a), "l"(b), "l"(c))
#define PACK_F32X2(out, lo, hi) \
    asm("mov.b64 %0, {%1, %2};" : "=l"(out) : "f"(lo), "f"(hi))
#define UNPACK_F32X2(lo, hi, in) \
    asm("mov.b64 {%0, %1}, %2;" : "=f"(lo), "=f"(hi) : "l"(in))

// Per-(dir,batch,y-tile) partial mins. Plain stores, no init, no atomics.
__device__ float g_part[NDB * YC * NP];
__device__ float g_psum[RBLOCKS];

__global__ __launch_bounds__(THREADS, 3) void chamfer_kernel(
    const float* __restrict__ x, const float* __restrict__ y) {
    // Two y-points per entry; one LDS.128 yields two packed f32x2 operands:
    //   sA[jp] = {nx_j0, nx_j1, ny_j0, ny_j1}
    //   sB[jp] = {nz_j0, nz_j1, pp_j0, pp_j1}
    // Padded by 1 entry for depth-1 prefetch overrun.
    __shared__ float4 sA[YP + 1], sB[YP + 1];

    const int yc   = blockIdx.x;
    const int xc   = blockIdx.y;
    const int dirb = blockIdx.z;
    const int dir  = dirb >> 3;
    const int b    = dirb & 7;

    const float* A  = dir ? y : x;
    const float* P  = dir ? x : y;
    const float* Ab = A + b * 3 * NP;
    const float* Pb = P + b * 3 * NP;

    const int tid = threadIdx.x;

    // Stage y-tile (YP=128 entries; first 128 threads).
    if (tid < YP) {
        int jp = tid;
        int g0 = yc * YT + 2 * jp;
        int g1 = g0 + 1;
        float px0 = Pb[g0],          px1 = Pb[g1];
        float py0 = Pb[NP + g0],     py1 = Pb[NP + g1];
        float pz0 = Pb[2 * NP + g0], pz1 = Pb[2 * NP + g1];
        float pp0 = fmaf(pz0, pz0, fmaf(py0, py0, px0 * px0));
        float pp1 = fmaf(pz1, pz1, fmaf(py1, py1, px1 * px1));
        sA[jp] = make_float4(-2.0f * px0, -2.0f * px1, -2.0f * py0, -2.0f * py1);
        sB[jp] = make_float4(-2.0f * pz0, -2.0f * pz1, pp0, pp1);
    }
    if (tid == 0) {  // init pad (never used in a min, just read)
        sA[YP] = make_float4(0.f, 0.f, 0.f, 0.f);
        sB[YP] = make_float4(0.f, 0.f, 0.f, 0.f);
    }
    __syncthreads();

    // Duplicated-packed x operands (loop invariant).
    unsigned long long axd[ILX], ayd[ILX], azd[ILX];
    float aa[ILX], mn[ILX];
#pragma unroll
    for (int k = 0; k < ILX; k++) {
        int gi = xc * XCHUNK + k * THREADS + tid;
        float ax = Ab[gi], ay = Ab[NP + gi], az = Ab[2 * NP + gi];
        PACK_F32X2(axd[k], ax, ax);
        PACK_F32X2(ayd[k], ay, ay);
        PACK_F32X2(azd[k], az, az);
        aa[k] = fmaf(az, az, fmaf(ay, ay, ax * ax));
        mn[k] = CUDART_INF_F;
    }

    // Depth-1 software pipeline: prefetch next jp while computing current.
    ulonglong2 va = *reinterpret_cast<const ulonglong2*>(&sA[0]);
    ulonglong2 vb = *reinterpret_cast<const ulonglong2*>(&sB[0]);
#pragma unroll 4
    for (int jp = 0; jp < YP; jp++) {
        ulonglong2 nva = *reinterpret_cast<const ulonglong2*>(&sA[jp + 1]);
        ulonglong2 nvb = *reinterpret_cast<const ulonglong2*>(&sB[jp + 1]);
        const unsigned long long mx = va.x;  // {nx0, nx1}
        const unsigned long long my = va.y;  // {ny0, ny1}
        const unsigned long long mz = vb.x;  // {nz0, nz1}
        const unsigned long long pp = vb.y;  // {pp0, pp1}
#pragma unroll
        for (int k = 0; k < ILX; k++) {
            unsigned long long t;
            FMA_F32X2(t, axd[k], mx, pp);
            FMA_F32X2(t, ayd[k], my, t);
            FMA_F32X2(t, azd[k], mz, t);
            float lo, hi;
            UNPACK_F32X2(lo, hi, t);
            mn[k] = fminf(mn[k], fminf(lo, hi));  // short carried chain
        }
        va = nva;
        vb = nvb;
    }

    float* gp = g_part + (dirb * YC + yc) * NP;
#pragma unroll
    for (int k = 0; k < ILX; k++) {
        int gi = xc * XCHUNK + k * THREADS + tid;
        gp[gi] = aa[k] + mn[k];
    }
}

// Stage A: min over the YC partial tiles, accumulate per-block sums.
__global__ __launch_bounds__(256) void reduceA_kernel() {
    __shared__ float sred[256];
    const int tid = threadIdx.x;
    float s = 0.0f;
#pragma unroll
    for (int k = 0; k < 4; k++) {
        int pt = blockIdx.x * 1024 + k * 256 + tid;  // global point 0..65535
        int db = pt >> 12;
        int p  = pt & (NP - 1);
        const float* gp = g_part + db * YC * NP + p;
        float m = gp[0];
#pragma unroll
        for (int yc = 1; yc < YC; yc++) m = fminf(m, gp[yc * NP]);
        s += m;
    }
    sred[tid] = s;
    __syncthreads();
    for (int w = 128; w > 0; w >>= 1) {
        if (tid < w) sred[tid] += sred[tid + w];
        __syncthreads();
    }
    if (tid == 0) g_psum[blockIdx.x] = sred[0];
}

// Stage B: final scalar.
__global__ void reduceB_kernel(float* __restrict__ out) {
    __shared__ float sred[RBLOCKS];
    int tid = threadIdx.x;
    sred[tid] = g_psum[tid];
    __syncthreads();
    for (int w = RBLOCKS / 2; w > 0; w >>= 1) {
        if (tid < w) sred[tid] += sred[tid + w];
        __syncthreads();
    }
    if (tid == 0) out[0] = sred[0] / (float)(NB * NP);
}

extern "C" void kernel_launch(void* const* d_in, const int* in_sizes, int n_in,
                              void* d_out, int out_size) {
    const float* x = (const float*)d_in[0];
    const float* y = (const float*)d_in[1];
    float* out = (float*)d_out;

    dim3 grid(YC, XC, NDB);  // 16 x 4 x 16 = 1024 blocks
    chamfer_kernel<<<grid, THREADS>>>(x, y);
    reduceA_kernel<<<RBLOCKS, 256>>>();
    reduceB_kernel<<<1, RBLOCKS>>>(out);
}